// round 16
// baseline (speedup 1.0000x reference)
#include <cuda_runtime.h>

#define LSEQ 65536
#define NB 32
#define NC 16
#define KW 8
#define THRV 0.25f
#define BETA 15.0f
#define XSC 20.0f

#define TS 36                          // tile row stride: 32 steps + carry(32) + pad
#define WT (32 * TS)                   // 1152 floats per warp tile
#define TBUF (16 * WT)                 // one tile buffer: 18432 floats
#define XROW (32 * TS)                 // one x row: 32 pieces x 36
#define XBUF (2 * XROW)                // one x stage buffer (both channels)
#define SMEM_FLOATS (2 * TBUF + 2 * XBUF)   // 41472
#define SMEM_BYTES (SMEM_FLOATS * 4)        // 165888 -> 1 block/SM, 128 regs/thread

__device__ __forceinline__ float softplusf(float x) {
    return (x > 0.f) ? (x + log1pf(expf(-x))) : log1pf(expf(x));
}

// 256 blocks x 512 threads, ONE block/SM (116+ regs/thread). block=(b, eighth);
// warp w = channel; lane owns a 256-step chunk, warmed up 32 steps from v=0
// (staged, zero-primed window; spike resets re-synchronize exactly).
// 8 phases x 32 steps, DOUBLE-BUFFERED vp tiles. Phase p interleaves, between
// its compute groups: (a) warp-local drain of phase p-1 (I/z/s stores spread
// across the phase) and (b) the cross-warp logits max of phase p-1, split by
// channel groups (both read the COMPLETED other buffer). ONE barrier/phase.
//   s = (vp>=THR); z = fma(BETA,vp,-BETA*THR); v_prev=(vp_prev>=THR)?0:vp_prev
//   I = (vp - alpha*v_prev)/(1-alpha)        (conv emits (1-alpha)*I)
//   logits = fma(BETA, max_c vp, -BETA*THR)  (monotone => bitwise-identical)
__global__ __launch_bounds__(512, 1) void snn_fused(
    const float* __restrict__ x,
    const float* __restrict__ wa, const float* __restrict__ wb,
    const float* __restrict__ rta, const float* __restrict__ rtb,
    const float* __restrict__ rga, const float* __restrict__ rgb,
    float* __restrict__ outI, float* __restrict__ outZ,
    float* __restrict__ outS, float* __restrict__ outL)
{
    extern __shared__ float smem[];
    float* tV = smem;                          // [2][16][32][36] vp tiles
    float* sx = smem + 2 * TBUF;               // [2][2][32][36] staged x

    const int b = blockIdx.x >> 3;
    const int eighth = blockIdx.x & 7;
    const int tid = threadIdx.x;
    const int w = tid >> 5;            // channel 0..15
    const int lane = tid & 31;
    const int fidx = w & 7;
    const int isB = w >> 3;

    const float* wrow = (isB ? wb : wa) + fidx * KW;
    const float rt = (isB ? rtb : rta)[fidx];
    const float rg = (isB ? rgb : rga)[0];

    float wo[KW];
    float nsq = 0.f;
#pragma unroll
    for (int k = 0; k < KW; k++) { wo[k] = wrow[k]; nsq = fmaf(wo[k], wo[k], nsq); }
    float norm = sqrtf(nsq);
    if (norm < 1e-8f) norm = 1e-8f;
    const float g = softplusf(rg) + 1e-4f;

    const float alpha = expf(-1.0f / (softplusf(rt) + 1e-4f));
    const float oma = 1.0f - alpha;
    const float inv_oma = 1.0f / oma;
    const float nBT = -BETA * THRV;

    const float scale = g * XSC / norm * oma;   // conv directly yields (1-a)*I
#pragma unroll
    for (int k = 0; k < KW; k++) wo[k] *= scale;

    const int p0 = eighth * 8192 + lane * 256;
    const int warm = (p0 == 0) ? 0 : 32;

    // x-stage mapping: threads 0-255 -> x row 0, 256-511 -> x row 1.
    const int sr = tid >> 8;
    const int tt = tid & 255;
    const int spiece = tt >> 3;
    const int sq = (tt & 7) * 4;
    const float* xrow = x + ((size_t)(b * 2 + sr) << 16);
    const float* sgbase = xrow + (size_t)(eighth * 8192 + spiece * 256 + sq);
    float* sxdst0 = sx + sr * XROW + spiece * TS + sq;   // buffer 0 slot

    // ---- stage warmup x into sx[0]: piece p needs x[p*256-32 .. p*256) ----
    {
        int woff = eighth * 8192 + spiece * 256 - 32 + sq;
        if (woff < 0) woff = 0;   // only piece 0 of eighth 0; its lane skips warmup
        *(float4*)sxdst0 = *(const float4*)(xrow + woff);
    }
    __syncthreads();

    // conv window zero-primed (effective ~25 exact warm steps + exact spike sync)
    float xw[12];
#pragma unroll
    for (int k = 0; k < 8; k++) xw[k] = 0.f;

    float vp = 0.f;   // pre-reset membrane of previous step

    const float* sxrow0 = sx + isB * XROW + lane * TS;

    // ---- warmup (0 or 32 steps) from staged x, no emission ----
    for (int gg = 0; gg < (warm >> 2); ++gg) {
        float4 xv = *(const float4*)(sxrow0 + gg * 4);
        xw[8] = xv.x; xw[9] = xv.y; xw[10] = xv.z; xw[11] = xv.w;
#pragma unroll
        for (int k = 0; k < 4; k++) {
            float I = 0.f;
#pragma unroll
            for (int j = 0; j < 8; j++) I = fmaf(wo[j], xw[k + 1 + j], I);
            float cand = fmaf(alpha, vp, I);
            vp = (vp >= THRV) ? I : cand;
        }
#pragma unroll
        for (int j = 0; j < 8; j++) xw[j] = xw[j + 4];
    }
    __syncthreads();   // warmup reads done; sx[0] free

    // stage x for phase 0 into sx[0]
    *(float4*)sxdst0 = *(const float4*)(sgbase);
    __syncthreads();

    const size_t seqoff = ((size_t)(b * NC + w)) << 16;
    const int rsub = lane >> 3;          // 0..3
    const int cq = (lane & 7) * 4;       // 0,4,...,28
    const int cidx = (cq == 0) ? 32 : (cq - 1);   // vp_prev source col (32 = carry)
    const int lj = tid >> 3;             // logits row (tid<256)
    const int lq = (tid & 7) * 4;        // logits quad

#pragma unroll 1
    for (int ph = 0; ph < 8; ++ph) {
        float* tVc = tV + (ph & 1) * TBUF;                 // compute target
        float* tVdBase = tV + ((ph & 1) ^ 1) * TBUF;       // ph-1 buffer
        float* mtVd = tVdBase + w * WT;                    // drain source
        float* rowV = tVc + w * WT + lane * TS;
        const float* sxrow = sxrow0 + (ph & 1) * XBUF;
        const size_t lbaseP = (size_t)(eighth * 8192 + (ph - 1) * 32);
        const bool do_drain = (ph > 0);
        const bool do_logit = (ph > 0) && (tid < 256);

        // issue next phase's x gather at phase top; STS near the barrier
        float4 stg;
        const bool do_stage = (ph < 7);
        if (do_stage) stg = *(const float4*)(sgbase + (ph + 1) * 32);

        // carry: post-reset v at phase entry (always < THR)
        rowV[32] = (vp >= THRV) ? 0.f : vp;

        float4 macc;   // logits running max (threads < 256)

        // ---- 4 subphases: 8 compute steps + 2 drain iters + 4 logit chans ----
#pragma unroll
        for (int sp = 0; sp < 4; ++sp) {
            float4 xq0 = *(const float4*)(sxrow + sp * 8);
            float4 xq1 = *(const float4*)(sxrow + sp * 8 + 4);
#pragma unroll
            for (int gg = 0; gg < 2; ++gg) {
                float4 xv = gg ? xq1 : xq0;
                xw[8] = xv.x; xw[9] = xv.y; xw[10] = xv.z; xw[11] = xv.w;
                float v4[4];
#pragma unroll
                for (int k = 0; k < 4; k++) {
                    float I = 0.f;
#pragma unroll
                    for (int j = 0; j < 8; j++) I = fmaf(wo[j], xw[k + 1 + j], I);
                    float cand = fmaf(alpha, vp, I);
                    vp = (vp >= THRV) ? I : cand;       // vp = vpre_t
                    v4[k] = vp;
                }
                *(float4*)(rowV + sp * 8 + gg * 4) = make_float4(v4[0], v4[1], v4[2], v4[3]);
#pragma unroll
                for (int j = 0; j < 8; j++) xw[j] = xw[j + 4];
            }
            // drain 2 iters of PREVIOUS phase's tile (own-warp rows, other buffer)
            if (do_drain) {
#pragma unroll
                for (int dd = 0; dd < 2; ++dd) {
                    const int r = (sp * 2 + dd) * 4 + rsub;
                    const float* rw = mtVd + r * TS;
                    float4 p4 = *(const float4*)(rw + cq);
                    float pz = rw[cidx];
                    float vprev = (pz >= THRV) ? 0.f : pz;
                    float4 vz;
                    vz.x = fmaf(BETA, p4.x, nBT);
                    vz.y = fmaf(BETA, p4.y, nBT);
                    vz.z = fmaf(BETA, p4.z, nBT);
                    vz.w = fmaf(BETA, p4.w, nBT);
                    float4 vs;
                    vs.x = (p4.x >= THRV) ? 1.f : 0.f;
                    vs.y = (p4.y >= THRV) ? 1.f : 0.f;
                    vs.z = (p4.z >= THRV) ? 1.f : 0.f;
                    vs.w = (p4.w >= THRV) ? 1.f : 0.f;
                    float4 vi;
                    vi.x = (p4.x - alpha * vprev) * inv_oma;
                    vi.y = (p4.y - alpha * ((p4.x >= THRV) ? 0.f : p4.x)) * inv_oma;
                    vi.z = (p4.z - alpha * ((p4.y >= THRV) ? 0.f : p4.y)) * inv_oma;
                    vi.w = (p4.w - alpha * ((p4.z >= THRV) ? 0.f : p4.z)) * inv_oma;
                    const size_t gi = seqoff + lbaseP + (size_t)r * 256 + cq;
                    __stcs((float4*)(outI + gi), vi);
                    __stcs((float4*)(outZ + gi), vz);
                    __stcs((float4*)(outS + gi), vs);
                }
            }
            // logits partial for PREVIOUS phase: channels [4sp, 4sp+4)
            if (do_logit) {
                const float* p = tVdBase + (sp * 4) * WT + lj * TS + lq;
                float4 t0 = *(const float4*)p;
                if (sp == 0) { macc = t0; }
                else {
                    macc.x = fmaxf(macc.x, t0.x); macc.y = fmaxf(macc.y, t0.y);
                    macc.z = fmaxf(macc.z, t0.z); macc.w = fmaxf(macc.w, t0.w);
                }
#pragma unroll
                for (int c2 = 1; c2 < 4; ++c2) {
                    float4 t4 = *(const float4*)(p + c2 * WT);
                    macc.x = fmaxf(macc.x, t4.x); macc.y = fmaxf(macc.y, t4.y);
                    macc.z = fmaxf(macc.z, t4.z); macc.w = fmaxf(macc.w, t4.w);
                }
            }
        }

        // finalize logits(ph-1)
        if (do_logit) {
            float4 m = macc;
            m.x = fmaf(BETA, m.x, nBT); m.y = fmaf(BETA, m.y, nBT);
            m.z = fmaf(BETA, m.z, nBT); m.w = fmaf(BETA, m.w, nBT);
            const size_t gl = (((size_t)b) << 16)
                            + (size_t)(eighth * 8192 + lj * 256 + (ph - 1) * 32 + lq);
            __stcs((float4*)(outL + gl), m);
        }

        // stage sx for next phase (other buffer; readers use current buffer)
        if (do_stage) *(float4*)(sxdst0 + ((ph + 1) & 1) * XBUF) = stg;
        __syncthreads();   // tiles of ph complete; ph-1 buffer now reusable
    }

    // ---- epilogue: drain + logits of phase 7 (tV[1]) ----
    {
        float* tVdBase = tV + TBUF;
        float* mtVd = tVdBase + w * WT;
        const size_t lbaseP = (size_t)(eighth * 8192 + 7 * 32);
#pragma unroll
        for (int it = 0; it < 8; ++it) {
            const int r = it * 4 + rsub;
            const float* rw = mtVd + r * TS;
            float4 p4 = *(const float4*)(rw + cq);
            float pz = rw[cidx];
            float vprev = (pz >= THRV) ? 0.f : pz;
            float4 vz;
            vz.x = fmaf(BETA, p4.x, nBT);
            vz.y = fmaf(BETA, p4.y, nBT);
            vz.z = fmaf(BETA, p4.z, nBT);
            vz.w = fmaf(BETA, p4.w, nBT);
            float4 vs;
            vs.x = (p4.x >= THRV) ? 1.f : 0.f;
            vs.y = (p4.y >= THRV) ? 1.f : 0.f;
            vs.z = (p4.z >= THRV) ? 1.f : 0.f;
            vs.w = (p4.w >= THRV) ? 1.f : 0.f;
            float4 vi;
            vi.x = (p4.x - alpha * vprev) * inv_oma;
            vi.y = (p4.y - alpha * ((p4.x >= THRV) ? 0.f : p4.x)) * inv_oma;
            vi.z = (p4.z - alpha * ((p4.y >= THRV) ? 0.f : p4.y)) * inv_oma;
            vi.w = (p4.w - alpha * ((p4.z >= THRV) ? 0.f : p4.z)) * inv_oma;
            const size_t gi = seqoff + lbaseP + (size_t)r * 256 + cq;
            __stcs((float4*)(outI + gi), vi);
            __stcs((float4*)(outZ + gi), vz);
            __stcs((float4*)(outS + gi), vs);
        }
        if (tid < 256) {
            const float* p = tVdBase + lj * TS + lq;
            float4 m = *(const float4*)p;
#pragma unroll
            for (int c2 = 1; c2 < 16; ++c2) {
                float4 t4 = *(const float4*)(p + c2 * WT);
                m.x = fmaxf(m.x, t4.x); m.y = fmaxf(m.y, t4.y);
                m.z = fmaxf(m.z, t4.z); m.w = fmaxf(m.w, t4.w);
            }
            m.x = fmaf(BETA, m.x, nBT); m.y = fmaf(BETA, m.y, nBT);
            m.z = fmaf(BETA, m.z, nBT); m.w = fmaf(BETA, m.w, nBT);
            const size_t gl = (((size_t)b) << 16)
                            + (size_t)(eighth * 8192 + lj * 256 + 7 * 32 + lq);
            __stcs((float4*)(outL + gl), m);
        }
    }
}

extern "C" void kernel_launch(void* const* d_in, const int* in_sizes, int n_in,
                              void* d_out, int out_size)
{
    const float* x   = (const float*)d_in[0];
    const float* wa  = (const float*)d_in[1];
    const float* wb  = (const float*)d_in[2];
    const float* rta = (const float*)d_in[3];
    const float* rtb = (const float*)d_in[4];
    const float* rga = (const float*)d_in[5];
    const float* rgb = (const float*)d_in[6];

    float* out = (float*)d_out;
    const size_t plane = (size_t)NB * NC * LSEQ;   // 33554432
    float* outI = out;
    float* outZ = out + plane;
    float* outS = out + 2 * plane;
    float* outL = out + 3 * plane;

    cudaFuncSetAttribute(snn_fused, cudaFuncAttributeMaxDynamicSharedMemorySize, SMEM_BYTES);
    snn_fused<<<256, 512, SMEM_BYTES>>>(x, wa, wb, rta, rtb, rga, rgb,
                                        outI, outZ, outS, outL);
}